// round 1
// baseline (speedup 1.0000x reference)
#include <cuda_runtime.h>
#include <cuda_fp16.h>
#include <cstdint>

// Problem constants
#define MTOT   8192          // B*S = 4*2048
#define IN_CH  256
#define NEXP   8
#define NBASIS 13
#define KTOT   2048          // IN_CH * NEXP
#define NTOT   256           // OUT

// Scratch (device globals; allocation-free per harness rules)
__device__ __half g_A[(size_t)MTOT * KTOT];    // eo, row-major [m][k], fp16 (32 MB)
__device__ __half g_Bm[(size_t)KTOT * NTOT];   // softmax gates, [k][o], fp16 (1 MB)

// ---------------------------------------------------------------------------
// Kernel 1: gates = softmax(gating_weights, axis=-1), laid out as G[k=i*8+e][o]
// gating_weights: (I=256, O=256, E=8), e contiguous.
// ---------------------------------------------------------------------------
__global__ void prep_G_kernel(const float* __restrict__ gw) {
    int t = blockIdx.x * 256 + threadIdx.x;       // t = i*256 + o, 65536 total
    int o = t & 255;
    int i = t >> 8;
    const float* g = gw + (size_t)t * NEXP;
    float v[NEXP];
    float mx = -1e30f;
#pragma unroll
    for (int e = 0; e < NEXP; e++) { v[e] = g[e]; mx = fmaxf(mx, v[e]); }
    float s = 0.f;
#pragma unroll
    for (int e = 0; e < NEXP; e++) { v[e] = __expf(v[e] - mx); s += v[e]; }
    float inv = 1.0f / s;
#pragma unroll
    for (int e = 0; e < NEXP; e++) {
        g_Bm[(size_t)(i * NEXP + e) * NTOT + o] = __float2half(v[e] * inv);
    }
}

// ---------------------------------------------------------------------------
// Kernel 2: eo[m][i*8+e] = sum_j basis_j(x[m,i]) * coeff[e][k0+j], fp16 out.
// Closed-form uniform cubic B-spline: only 4 nonzero basis values.
// ---------------------------------------------------------------------------
__global__ void prep_eo_kernel(const float* __restrict__ x,
                               const float* __restrict__ coeff) {
    __shared__ float C2[NBASIS][NEXP + 1];   // [n][e], pad to 9 -> conflict-free
    int tid = threadIdx.x;
    if (tid < NBASIS * NEXP) {
        int e = tid & 7, n = tid >> 3;       // tid = n*8 + e
        C2[n][e] = coeff[e * NBASIS + n];
    }
    __syncthreads();

    int t = blockIdx.x * 256 + tid;          // t = m*256 + i  (x is m-major, i contig)
    float xv = x[t];
    xv = fminf(fmaxf(xv, -1.0f), 1.0f - 1e-6f);
    float u = (xv + 1.0f) * 5.0f;            // (x+1)/h, h = 0.2
    int i0 = (int)u;
    i0 = i0 > 9 ? 9 : (i0 < 0 ? 0 : i0);
    u -= (float)i0;
    float om = 1.0f - u;
    float u2 = u * u, u3 = u2 * u;
    float bw[4];
    bw[0] = om * om * om * (1.0f / 6.0f);
    bw[1] = (3.0f * u3 - 6.0f * u2 + 4.0f) * (1.0f / 6.0f);
    bw[2] = (-3.0f * u3 + 3.0f * u2 + 3.0f * u + 1.0f) * (1.0f / 6.0f);
    bw[3] = u3 * (1.0f / 6.0f);

    float acc[NEXP];
#pragma unroll
    for (int e = 0; e < NEXP; e++) acc[e] = 0.f;
#pragma unroll
    for (int j = 0; j < 4; j++) {
        float w = bw[j];
        const float* row = C2[i0 + j];
#pragma unroll
        for (int e = 0; e < NEXP; e++) acc[e] += w * row[e];
    }
    union { uint4 v; __half2 h[4]; } uo;
#pragma unroll
    for (int p = 0; p < 4; p++)
        uo.h[p] = __floats2half2_rn(acc[2 * p], acc[2 * p + 1]);
    *(uint4*)(g_A + (size_t)t * NEXP) = uo.v;   // 16B aligned, coalesced
}

// ---------------------------------------------------------------------------
// Kernel 3: out[m][o] = sum_k A[m][k] * G[k][o]; M=8192, N=256, K=2048.
// fp16 mma.sync m16n8k16, fp32 accumulate. BM=128 BN=64 BK=32, 8 warps.
// ---------------------------------------------------------------------------
#define BM  128
#define BN  64
#define BK  32
#define AKP 40    // A smem row stride (halves): banks (20*row)%32 distinct per frag
#define BNP 72    // B smem row stride (halves): 144B => banks 4k, ldmatrix-clean

__device__ __forceinline__ uint32_t smem_addr(const void* p) {
    return (uint32_t)__cvta_generic_to_shared(p);
}

__device__ __forceinline__ void mma16816(float* d, const uint32_t* a,
                                         uint32_t b0, uint32_t b1) {
    asm volatile(
        "mma.sync.aligned.m16n8k16.row.col.f32.f16.f16.f32 "
        "{%0,%1,%2,%3}, {%4,%5,%6,%7}, {%8,%9}, {%0,%1,%2,%3};"
        : "+f"(d[0]), "+f"(d[1]), "+f"(d[2]), "+f"(d[3])
        : "r"(a[0]), "r"(a[1]), "r"(a[2]), "r"(a[3]), "r"(b0), "r"(b1));
}

__global__ __launch_bounds__(256, 2)
void gemm_kernel(float* __restrict__ C) {
    __shared__ __half As[2][BM * AKP];   // [m][k], padded
    __shared__ __half Bs[2][BK * BNP];   // [k][n], padded

    const int tid  = threadIdx.x;
    const int lane = tid & 31;
    const int warp = tid >> 5;
    const int wm = (warp & 3) * 32;      // 4 warps along M
    const int wn = (warp >> 2) * 32;     // 2 warps along N
    const int g  = lane >> 2;
    const int c2 = (lane & 3) * 2;

    const int m0 = blockIdx.x * BM;
    const int n0 = blockIdx.y * BN;

    const __half* Ag = g_A + (size_t)m0 * KTOT;
    const __half* Bg = g_Bm + n0;

    // global-load thread mapping
    const int ar0 = tid >> 2;            // A rows 0..63   (and +64 for second)
    const int acu = (tid & 3) * 8;       // A col (halves) within BK
    const int bkr = tid >> 3;            // B k-row 0..31
    const int bcu = (tid & 7) * 8;       // B col (halves) within BN

    float acc[2][4][4];
#pragma unroll
    for (int mi = 0; mi < 2; mi++)
#pragma unroll
        for (int jn = 0; jn < 4; jn++)
#pragma unroll
            for (int q = 0; q < 4; q++) acc[mi][jn][q] = 0.f;

    // prologue: tile 0 -> buffer 0
    {
        uint4 a0v = *(const uint4*)(Ag + (size_t)ar0 * KTOT + acu);
        uint4 a1v = *(const uint4*)(Ag + (size_t)(ar0 + 64) * KTOT + acu);
        uint4 bv  = *(const uint4*)(Bg + (size_t)bkr * NTOT + bcu);
        *(uint4*)&As[0][ar0 * AKP + acu]        = a0v;
        *(uint4*)&As[0][(ar0 + 64) * AKP + acu] = a1v;
        *(uint4*)&Bs[0][bkr * BNP + bcu]        = bv;
    }
    __syncthreads();

    const int NK = KTOT / BK;            // 64
    for (int kt = 0; kt < NK; kt++) {
        const int cur = kt & 1;
        uint4 a0v, a1v, bv;
        if (kt + 1 < NK) {               // stage next tile into registers
            const int kof = (kt + 1) * BK;
            a0v = *(const uint4*)(Ag + (size_t)ar0 * KTOT + kof + acu);
            a1v = *(const uint4*)(Ag + (size_t)(ar0 + 64) * KTOT + kof + acu);
            bv  = *(const uint4*)(Bg + (size_t)(kof + bkr) * NTOT + bcu);
        }

        const __half* Asb = As[cur];
        const __half* Bsb = Bs[cur];
#pragma unroll
        for (int s = 0; s < 2; s++) {    // two k16 steps per BK=32
            uint32_t a[2][4];
#pragma unroll
            for (int mi = 0; mi < 2; mi++) {
                const __half* p = Asb + (wm + mi * 16 + g) * AKP + s * 16 + c2;
                a[mi][0] = *(const uint32_t*)p;              // (g,      c2)
                a[mi][1] = *(const uint32_t*)(p + 8 * AKP);  // (g+8,    c2)
                a[mi][2] = *(const uint32_t*)(p + 8);        // (g,   c2+8)
                a[mi][3] = *(const uint32_t*)(p + 8 * AKP + 8);
            }
#pragma unroll
            for (int jn = 0; jn < 4; jn++) {
                uint32_t b0, b1;
                uint32_t ad = smem_addr(Bsb + (s * 16 + (lane & 15)) * BNP
                                            + wn + jn * 8);
                asm volatile(
                    "ldmatrix.sync.aligned.m8n8.x2.trans.shared.b16 {%0,%1}, [%2];"
                    : "=r"(b0), "=r"(b1) : "r"(ad));
#pragma unroll
                for (int mi = 0; mi < 2; mi++)
                    mma16816(acc[mi][jn], a[mi], b0, b1);
            }
        }

        if (kt + 1 < NK) {               // commit staged tile to other buffer
            const int nxt = cur ^ 1;
            *(uint4*)&As[nxt][ar0 * AKP + acu]        = a0v;
            *(uint4*)&As[nxt][(ar0 + 64) * AKP + acu] = a1v;
            *(uint4*)&Bs[nxt][bkr * BNP + bcu]        = bv;
        }
        __syncthreads();
    }

    // epilogue: fp32 out, 8B vector stores
#pragma unroll
    for (int mi = 0; mi < 2; mi++) {
#pragma unroll
        for (int jn = 0; jn < 4; jn++) {
            int row = m0 + wm + mi * 16 + g;
            int col = n0 + wn + jn * 8 + c2;
            float2 v0 = make_float2(acc[mi][jn][0], acc[mi][jn][1]);
            float2 v1 = make_float2(acc[mi][jn][2], acc[mi][jn][3]);
            *(float2*)&C[(size_t)row * NTOT + col]       = v0;
            *(float2*)&C[(size_t)(row + 8) * NTOT + col] = v1;
        }
    }
}

// ---------------------------------------------------------------------------
extern "C" void kernel_launch(void* const* d_in, const int* in_sizes, int n_in,
                              void* d_out, int out_size) {
    (void)in_sizes; (void)n_in; (void)out_size;
    const float* x     = (const float*)d_in[0];   // (4,2048,256) f32
    const float* coeff = (const float*)d_in[1];   // (8,13) f32
    const float* gw    = (const float*)d_in[2];   // (256,256,8) f32
    float* out = (float*)d_out;                   // (4,2048,256) f32

    prep_G_kernel<<<256, 256>>>(gw);
    prep_eo_kernel<<<MTOT * IN_CH / 256, 256>>>(x, coeff);
    dim3 grid(MTOT / BM, NTOT / BN);
    gemm_kernel<<<grid, 256>>>(out);
}